// round 14
// baseline (speedup 1.0000x reference)
#include <cuda_runtime.h>
#include <math.h>

#define NB 64
#define CC 256
#define TT 64
#define VV 25
#define HID 16
#define NCV (NB*CC)            // 16384 (n,c) chunks
#define CHUNK (TT*VV)          // 1600 floats per (n,c)

#define CPB 2                  // chunks per block
#define THREADS 256

#define G 4                    // pipeline groups
#define NBG (NB/G)             // 16 batches per group
#define GCH (NBG*CC)           // 4096 chunks per group (26.2 MB)
#define GBLK (GCH/CPB)         // 2048 blocks per group-pass

// scratch (allocation-free rule: __device__ globals)
__device__ float g_avg[NCV];
__device__ float g_mx[NCV];
__device__ float g_gates[NB * 5 * CC];

// output joint -> input joint (TORSO, LEFT_HAND, LEFT_LEG, RIGHT_HAND, RIGHT_LEG)
__constant__ int c_perm[VV] = {0,1,2,3,20,  8,9,10,11,23,24,  16,17,18,19,  4,5,6,7,21,22,  12,13,14,15};
__constant__ int c_grp[VV]  = {0,0,0,0,0,   1,1,1,1,1,1,      2,2,2,2,      3,3,3,3,3,3,    4,4,4,4};

// ---------------- reduce body: torso mean/max for CPB chunks at `base` ----------------
__device__ __forceinline__ void reduce_block(const float* __restrict__ x, int base,
                                             int tid, float* sx, float* ps, float* pm) {
    const float4* __restrict__ src = reinterpret_cast<const float4*>(x + (size_t)base * CHUNK);
#pragma unroll
    for (int idx = tid; idx < CPB * CHUNK / 4; idx += THREADS)
        reinterpret_cast<float4*>(sx)[idx] = src[idx];
    __syncthreads();

    const int cl = tid >> 7, r = tid & 127;
    float s = 0.f, m = -INFINITY;
    if (r < TT) {
        const float* row = sx + cl * CHUNK + r * VV;       // stride 25: conflict-free banks
        float v0 = row[0], v1 = row[1], v2 = row[2], v3 = row[3], v4 = row[20];
        s = (v0 + v1) + (v2 + v3) + v4;
        m = fmaxf(fmaxf(v0, v1), fmaxf(fmaxf(v2, v3), v4));
    }
#pragma unroll
    for (int o = 16; o; o >>= 1) {
        s += __shfl_xor_sync(0xffffffffu, s, o);
        m = fmaxf(m, __shfl_xor_sync(0xffffffffu, m, o));
    }
    const int wid = tid >> 5, lane = tid & 31;
    if (lane == 0) { ps[wid] = s; pm[wid] = m; }
    __syncthreads();
    if (tid < CPB) {
        g_avg[base + tid] = (ps[tid * 4] + ps[tid * 4 + 1]) * (1.0f / 320.0f);
        g_mx [base + tid] = fmaxf(pm[tid * 4], pm[tid * 4 + 1]);
    }
}

// ---------------- scale body: out = permute(x) * gates for CPB chunks at `base` ----------------
__device__ __forceinline__ void scale_block(const float* __restrict__ x, float* __restrict__ out,
                                            int base, int tid, float* sx, float* sgate, int* sperm) {
    const float4* __restrict__ src = reinterpret_cast<const float4*>(x + (size_t)base * CHUNK);
    float4* __restrict__ dst = reinterpret_cast<float4*>(out + (size_t)base * CHUNK);

    if (tid < VV) sperm[tid] = c_perm[tid];
    if (tid >= 32 && tid < 32 + CPB * VV) {
        int q = tid - 32, cl = q / VV, j = q - cl * VV;
        int nc = base + cl;
        sgate[cl * 32 + j] = g_gates[(nc >> 8) * (5 * CC) + c_grp[j] * CC + (nc & (CC - 1))];
    }
#pragma unroll
    for (int idx = tid; idx < CPB * CHUNK / 4; idx += THREADS)
        reinterpret_cast<float4*>(sx)[idx] = src[idx];
    __syncthreads();

#pragma unroll
    for (int idx = tid; idx < CPB * CHUNK / 4; idx += THREADS) {
        int e0 = idx * 4;
        int cl = e0 / CHUNK;
        int rem = e0 - cl * CHUNK;
        float r[4];
#pragma unroll
        for (int k = 0; k < 4; k++) {
            int e = rem + k;
            int t = e / VV;
            int j = e - t * VV;
            r[k] = sx[cl * CHUNK + t * VV + sperm[j]] * sgate[cl * 32 + j];
        }
        __stcs(&dst[idx], make_float4(r[0], r[1], r[2], r[3]));
    }
}

// ---------------- combined pipeline kernel: scale group sg (if >=0) + reduce group rg (if >=0) ----
// Branch is uniform per block (depends only on blockIdx) — no divergence across the block.
__global__ __launch_bounds__(THREADS) void comb_kernel(const float* __restrict__ x,
                                                       float* __restrict__ out,
                                                       int rg, int sg) {
    __shared__ float sx[CPB * CHUNK];      // 12.8 KB
    __shared__ float saux[64];             // reduce: ps=saux, pm=saux+8 | scale: sgate=saux
    __shared__ int   sperm[32];
    const int tid = threadIdx.x;

    const bool doScale = (sg >= 0) && (rg < 0 || blockIdx.x < GBLK);
    if (doScale) {
        const int sb = blockIdx.x;                               // 0..GBLK-1
        const int base = sg * GCH + (GBLK - 1 - sb) * CPB;       // LIFO within group
        scale_block(x, out, base, tid, sx, saux, sperm);
    } else {
        const int rb = blockIdx.x - ((sg >= 0) ? GBLK : 0);
        const int base = rg * GCH + rb * CPB;
        reduce_block(x, base, tid, sx, saux, saux + 8);
    }
}

// ---------------- mlp for one group of batches ----------------
__global__ void mlp_kernel(const float* __restrict__ W1, const float* __restrict__ b1,
                           const float* __restrict__ W2, const float* __restrict__ b2,
                           int n0) {
    int blk = blockIdx.x;          // local (n*5 + f)
    int n = n0 + blk / 5, f = blk % 5;
    __shared__ float pa[CC], pm[CC], hs[HID];
    int tid = threadIdx.x;
    pa[tid] = g_avg[n * CC + tid];
    pm[tid] = g_mx[n * CC + tid];
    __syncthreads();

    int w = tid >> 5, lane = tid & 31;   // 8 warps, 2 hidden units each
#pragma unroll
    for (int hh = 0; hh < 2; hh++) {
        int h = w * 2 + hh;
        const float* w1row = W1 + (f * HID + h) * CC;
        float sa = 0.f, sm = 0.f;
#pragma unroll
        for (int c = lane; c < CC; c += 32) {
            float wv = w1row[c];
            sa = fmaf(wv, pa[c], sa);
            sm = fmaf(wv, pm[c], sm);
        }
#pragma unroll
        for (int o = 16; o; o >>= 1) {
            sa += __shfl_xor_sync(0xffffffffu, sa, o);
            sm += __shfl_xor_sync(0xffffffffu, sm, o);
        }
        if (lane == 0) {
            float b = b1[f * HID + h];
            hs[h] = fmaxf(sa + b, 0.f) + fmaxf(sm + b, 0.f);
        }
    }
    __syncthreads();

    const float* w2row = W2 + ((size_t)f * CC + tid) * HID;
    float o = 2.0f * b2[f * CC + tid];
#pragma unroll
    for (int h = 0; h < HID; h++) o = fmaf(hs[h], w2row[h], o);
    g_gates[n * (5 * CC) + f * CC + tid] = 1.0f / (1.0f + expf(-o));
}

extern "C" void kernel_launch(void* const* d_in, const int* in_sizes, int n_in,
                              void* d_out, int out_size) {
    const float* x  = (const float*)d_in[0];
    const float* W1 = (const float*)d_in[1];
    const float* b1 = (const float*)d_in[2];
    const float* W2 = (const float*)d_in[3];
    const float* b2 = (const float*)d_in[4];
    float* out = (float*)d_out;

    // software pipeline over G groups: reduce(g) overlaps scale(g-1) in one kernel
    comb_kernel<<<GBLK, THREADS>>>(x, out, 0, -1);                 // reduce g0
    mlp_kernel<<<NBG * 5, 256>>>(W1, b1, W2, b2, 0);               // gates g0
    for (int g = 1; g < G; g++) {
        comb_kernel<<<2 * GBLK, THREADS>>>(x, out, g, g - 1);      // reduce g | scale g-1
        mlp_kernel<<<NBG * 5, 256>>>(W1, b1, W2, b2, g * NBG);     // gates g
    }
    comb_kernel<<<GBLK, THREADS>>>(x, out, -1, G - 1);             // scale g3
}

// round 15
// speedup vs baseline: 1.0951x; 1.0951x over previous
#include <cuda_runtime.h>
#include <math.h>

#define NB 64
#define CC 256
#define TT 64
#define VV 25
#define HID 16
#define NCV (NB*CC)            // 16384 (n,c) chunks
#define CHUNK (TT*VV)          // 1600 floats per (n,c)

#define CPB 2                  // chunks per block
#define THREADS 256

#define G 2                    // pipeline groups
#define NBG (NB/G)             // 32 batches per group
#define GCH (NBG*CC)           // 8192 chunks per group (52.4 MB)
#define GBLK (GCH/CPB)         // 4096 blocks per group-pass

// scratch (allocation-free rule: __device__ globals)
__device__ float g_avg[NCV];
__device__ float g_mx[NCV];
__device__ float g_gates[NB * 5 * CC];

// output joint -> input joint (TORSO, LEFT_HAND, LEFT_LEG, RIGHT_HAND, RIGHT_LEG)
__constant__ int c_perm[VV] = {0,1,2,3,20,  8,9,10,11,23,24,  16,17,18,19,  4,5,6,7,21,22,  12,13,14,15};
__constant__ int c_grp[VV]  = {0,0,0,0,0,   1,1,1,1,1,1,      2,2,2,2,      3,3,3,3,3,3,    4,4,4,4};

// ---------------- reduce body: torso mean/max for CPB chunks at `base` ----------------
__device__ __forceinline__ void reduce_block(const float* __restrict__ x, int base,
                                             int tid, float* sx, float* ps, float* pm) {
    const float4* __restrict__ src = reinterpret_cast<const float4*>(x + (size_t)base * CHUNK);
#pragma unroll
    for (int idx = tid; idx < CPB * CHUNK / 4; idx += THREADS)
        reinterpret_cast<float4*>(sx)[idx] = src[idx];
    __syncthreads();

    const int cl = tid >> 7, r = tid & 127;
    float s = 0.f, m = -INFINITY;
    if (r < TT) {
        const float* row = sx + cl * CHUNK + r * VV;       // stride 25: conflict-free banks
        float v0 = row[0], v1 = row[1], v2 = row[2], v3 = row[3], v4 = row[20];
        s = (v0 + v1) + (v2 + v3) + v4;
        m = fmaxf(fmaxf(v0, v1), fmaxf(fmaxf(v2, v3), v4));
    }
#pragma unroll
    for (int o = 16; o; o >>= 1) {
        s += __shfl_xor_sync(0xffffffffu, s, o);
        m = fmaxf(m, __shfl_xor_sync(0xffffffffu, m, o));
    }
    const int wid = tid >> 5, lane = tid & 31;
    if (lane == 0) { ps[wid] = s; pm[wid] = m; }
    __syncthreads();
    if (tid < CPB) {
        g_avg[base + tid] = (ps[tid * 4] + ps[tid * 4 + 1]) * (1.0f / 320.0f);
        g_mx [base + tid] = fmaxf(pm[tid * 4], pm[tid * 4 + 1]);
    }
}

// ---------------- scale body: out = permute(x) * gates for CPB chunks at `base` ----------------
__device__ __forceinline__ void scale_block(const float* __restrict__ x, float* __restrict__ out,
                                            int base, int tid, float* sx, float* sgate, int* sperm) {
    const float4* __restrict__ src = reinterpret_cast<const float4*>(x + (size_t)base * CHUNK);
    float4* __restrict__ dst = reinterpret_cast<float4*>(out + (size_t)base * CHUNK);

    if (tid < VV) sperm[tid] = c_perm[tid];
    if (tid >= 32 && tid < 32 + CPB * VV) {
        int q = tid - 32, cl = q / VV, j = q - cl * VV;
        int nc = base + cl;
        sgate[cl * 32 + j] = g_gates[(nc >> 8) * (5 * CC) + c_grp[j] * CC + (nc & (CC - 1))];
    }
#pragma unroll
    for (int idx = tid; idx < CPB * CHUNK / 4; idx += THREADS)
        reinterpret_cast<float4*>(sx)[idx] = src[idx];
    __syncthreads();

#pragma unroll
    for (int idx = tid; idx < CPB * CHUNK / 4; idx += THREADS) {
        int e0 = idx * 4;
        int cl = e0 / CHUNK;
        int rem = e0 - cl * CHUNK;
        float r[4];
#pragma unroll
        for (int k = 0; k < 4; k++) {
            int e = rem + k;
            int t = e / VV;
            int j = e - t * VV;
            r[k] = sx[cl * CHUNK + t * VV + sperm[j]] * sgate[cl * 32 + j];
        }
        __stcs(&dst[idx], make_float4(r[0], r[1], r[2], r[3]));
    }
}

// ---------------- combined pipeline kernel: scale group sg (if >=0) + reduce group rg (if >=0) ----
// First launch (rg==0, sg<0) also prefetches the MLP weights into L2 so mlp_kernel's
// weight loads become L2 hits instead of cold DRAM (mlp was 6us latency-bound).
__global__ __launch_bounds__(THREADS) void comb_kernel(const float* __restrict__ x,
                                                       float* __restrict__ out,
                                                       const float* __restrict__ W1,
                                                       const float* __restrict__ W2,
                                                       const float* __restrict__ b2,
                                                       int rg, int sg) {
    __shared__ float sx[CPB * CHUNK];      // 12.8 KB
    __shared__ float saux[64];             // reduce: ps/pm | scale: sgate
    __shared__ int   sperm[32];
    const int tid = threadIdx.x;

    if (rg == 0 && sg < 0 && blockIdx.x < 8) {   // prefetch ~170 KB of weights into L2
        const int gid = blockIdx.x * THREADS + tid;   // 0..2047, 128B lines
        if (gid < 640) {                              // W1: 20480 floats
            asm volatile("prefetch.global.L2 [%0];" :: "l"(W1 + gid * 32));
            asm volatile("prefetch.global.L2 [%0];" :: "l"(W2 + gid * 32));   // W2: 20480
        }
        if (gid < 40)
            asm volatile("prefetch.global.L2 [%0];" :: "l"(b2 + gid * 32));   // b2: 1280
    }

    const bool doScale = (sg >= 0) && (rg < 0 || blockIdx.x < GBLK);
    if (doScale) {
        const int sb = blockIdx.x;                               // 0..GBLK-1
        const int base = sg * GCH + (GBLK - 1 - sb) * CPB;       // LIFO within group
        scale_block(x, out, base, tid, sx, saux, sperm);
    } else {
        const int rb = blockIdx.x - ((sg >= 0) ? GBLK : 0);
        const int base = rg * GCH + rb * CPB;
        reduce_block(x, base, tid, sx, saux, saux + 8);
    }
}

// ---------------- mlp for one group of batches ----------------
__global__ void mlp_kernel(const float* __restrict__ W1, const float* __restrict__ b1,
                           const float* __restrict__ W2, const float* __restrict__ b2,
                           int n0) {
    int blk = blockIdx.x;          // local (n*5 + f)
    int n = n0 + blk / 5, f = blk % 5;
    __shared__ float pa[CC], pm[CC], hs[HID];
    int tid = threadIdx.x;
    pa[tid] = g_avg[n * CC + tid];
    pm[tid] = g_mx[n * CC + tid];
    __syncthreads();

    int w = tid >> 5, lane = tid & 31;   // 8 warps, 2 hidden units each
#pragma unroll
    for (int hh = 0; hh < 2; hh++) {
        int h = w * 2 + hh;
        const float* w1row = W1 + (f * HID + h) * CC;
        float sa = 0.f, sm = 0.f;
#pragma unroll
        for (int c = lane; c < CC; c += 32) {
            float wv = w1row[c];
            sa = fmaf(wv, pa[c], sa);
            sm = fmaf(wv, pm[c], sm);
        }
#pragma unroll
        for (int o = 16; o; o >>= 1) {
            sa += __shfl_xor_sync(0xffffffffu, sa, o);
            sm += __shfl_xor_sync(0xffffffffu, sm, o);
        }
        if (lane == 0) {
            float b = b1[f * HID + h];
            hs[h] = fmaxf(sa + b, 0.f) + fmaxf(sm + b, 0.f);
        }
    }
    __syncthreads();

    const float* w2row = W2 + ((size_t)f * CC + tid) * HID;
    float o = 2.0f * b2[f * CC + tid];
#pragma unroll
    for (int h = 0; h < HID; h++) o = fmaf(hs[h], w2row[h], o);
    g_gates[n * (5 * CC) + f * CC + tid] = 1.0f / (1.0f + expf(-o));
}

extern "C" void kernel_launch(void* const* d_in, const int* in_sizes, int n_in,
                              void* d_out, int out_size) {
    const float* x  = (const float*)d_in[0];
    const float* W1 = (const float*)d_in[1];
    const float* b1 = (const float*)d_in[2];
    const float* W2 = (const float*)d_in[3];
    const float* b2 = (const float*)d_in[4];
    float* out = (float*)d_out;

    // 2-stage software pipeline: reduce(g1) overlaps scale(g0) inside one kernel.
    comb_kernel<<<GBLK, THREADS>>>(x, out, W1, W2, b2, 0, -1);       // reduce g0 (+weight prefetch)
    mlp_kernel<<<NBG * 5, 256>>>(W1, b1, W2, b2, 0);                 // gates g0 (L2-hot weights)
    comb_kernel<<<2 * GBLK, THREADS>>>(x, out, W1, W2, b2, 1, 0);    // reduce g1 | scale g0
    mlp_kernel<<<NBG * 5, 256>>>(W1, b1, W2, b2, NBG);               // gates g1
    comb_kernel<<<GBLK, THREADS>>>(x, out, W1, W2, b2, -1, 1);       // scale g1
}